// round 3
// baseline (speedup 1.0000x reference)
#include <cuda_runtime.h>
#include <math.h>

// Problem constants
#define BB 2
#define TT 2048
#define HH 16
#define DD 64
#define CC 1024          // HH*DD
#define BT (BB*TT)       // 4096
#define BH (BB*HH)       // 32

// Scratch in __device__ globals (no allocation allowed in kernel_launch)
__device__ float g_q[BH * TT * DD];   // [b,h,t,d]
__device__ float g_k[BH * TT * DD];   // [b,h,t,d]
__device__ float g_v[BH * TT * DD];   // [b,h,t,d]  (head-mixed V)
__device__ float g_y[BB * TT * HH * DD]; // [b,t,h,d]

// ---------------------------------------------------------------------------
// Kernel 1: qk = x @ W_attn, split into q/k and store in [b,h,t,d] layout.
// 64x64 tile, BK=16, 4x4 register micro-tile, 256 threads.
// ---------------------------------------------------------------------------
__global__ __launch_bounds__(256) void gemm_qk_kernel(
    const float* __restrict__ x, const float* __restrict__ W)
{
    __shared__ float As[16][68];   // [k][m], padded
    __shared__ float Bs[16][64];   // [k][n]

    const int tid = threadIdx.x;
    const int m0 = blockIdx.y * 64;
    const int n0 = blockIdx.x * 64;
    const int tx = tid & 15;       // n micro
    const int ty = tid >> 4;       // m micro

    // loader indices
    const int lm  = tid >> 2;      // 0..63 row of x tile
    const int lk4 = tid & 3;       // float4 along k
    const int lr  = tid >> 4;      // 0..15 row of W tile
    const int lc4 = tid & 15;      // float4 along n

    float acc[4][4] = {};

    for (int k0 = 0; k0 < CC; k0 += 16) {
        float4 av = *(const float4*)&x[(size_t)(m0 + lm) * CC + k0 + lk4 * 4];
        float4 bv = *(const float4*)&W[(size_t)(k0 + lr) * (2 * CC) + n0 + lc4 * 4];
        __syncthreads();
        As[lk4 * 4 + 0][lm] = av.x;
        As[lk4 * 4 + 1][lm] = av.y;
        As[lk4 * 4 + 2][lm] = av.z;
        As[lk4 * 4 + 3][lm] = av.w;
        *(float4*)&Bs[lr][lc4 * 4] = bv;
        __syncthreads();
        #pragma unroll
        for (int kk = 0; kk < 16; kk++) {
            float4 a = *(float4*)&As[kk][ty * 4];
            float4 b = *(float4*)&Bs[kk][tx * 4];
            float ar[4] = {a.x, a.y, a.z, a.w};
            float br[4] = {b.x, b.y, b.z, b.w};
            #pragma unroll
            for (int i = 0; i < 4; i++)
                #pragma unroll
                for (int j = 0; j < 4; j++)
                    acc[i][j] += ar[i] * br[j];
        }
    }

    // n-tile of 64 aligns with one head and one of {q,k}
    const bool isq = (n0 < CC);
    const int  hh  = (n0 >> 6) & (HH - 1);
    float* dst = isq ? g_q : g_k;
    #pragma unroll
    for (int i = 0; i < 4; i++) {
        int m = m0 + ty * 4 + i;
        int b = m >> 11;           // /2048
        int t = m & (TT - 1);
        float4 v4 = make_float4(acc[i][0], acc[i][1], acc[i][2], acc[i][3]);
        *(float4*)&dst[(((size_t)(b * HH + hh) * TT) + t) * DD + tx * 4] = v4;
    }
}

// ---------------------------------------------------------------------------
// Kernel 2: v[b,j,t,d] = sum_i x[b,t,i*64+d] * v_tmp[i][j]   (head mixing)
// One block per (b,t) row. Memory-bound.
// ---------------------------------------------------------------------------
__global__ __launch_bounds__(256) void vmix_kernel(
    const float* __restrict__ x, const float* __restrict__ v_tmp)
{
    __shared__ float xs[CC];
    __shared__ float wt[HH * HH];
    const int bt  = blockIdx.x;
    const int tid = threadIdx.x;
    wt[tid] = v_tmp[tid];          // 256 == 16*16
    #pragma unroll
    for (int i = tid; i < CC; i += 256) xs[i] = x[(size_t)bt * CC + i];
    __syncthreads();
    const int b = bt >> 11;
    const int t = bt & (TT - 1);
    for (int o = tid; o < CC; o += 256) {
        int j = o >> 6, d = o & 63;
        float s = 0.f;
        #pragma unroll
        for (int i = 0; i < HH; i++) s += xs[i * DD + d] * wt[i * HH + j];
        g_v[(((size_t)(b * HH + j) * TT) + t) * DD + d] = s;
    }
}

// ---------------------------------------------------------------------------
// Kernel 3: flash-attention with causal + ALiBi.
// Block = (qtile of 64 queries) x (b,h). 256 threads, 16x16 thread grid,
// 4x4 micro-tiles. K/Q stored d-major (transposed) in smem for vectorized S.
// ---------------------------------------------------------------------------
#define STR 68   // smem row stride (floats); 68*4B = 272B keeps float4 align

__global__ __launch_bounds__(256) void attn_kernel()
{
    extern __shared__ float sm[];
    float* Qt = sm;                 // [d][r]  64 x STR
    float* Kt = Qt + 64 * STR;      // [d][c]
    float* Vs = Kt + 64 * STR;      // [c][d]
    float* Ss = Vs + 64 * STR;      // [r][c]
    float* m_row = Ss + 64 * STR;   // 64
    float* l_row = m_row + 64;      // 64
    float* c_row = l_row + 64;      // 64

    const int tid   = threadIdx.x;
    const int tx    = tid & 15;
    const int ty    = tid >> 4;
    const int qtile = blockIdx.x;
    const int bh    = blockIdx.y;
    const int q0    = qtile * 64;
    const int h     = bh & (HH - 1);
    const int b     = bh >> 4;

    const float* qp = g_q + (size_t)bh * TT * DD;
    const float* kp = g_k + (size_t)bh * TT * DD;
    const float* vp = g_v + (size_t)bh * TT * DD;

    const float slope = exp2f(-0.5f * (float)(h + 1));
    const float scale = 0.125f;     // 1/sqrt(64)

    // Load Q tile transposed: Qt[d][r]
    for (int idx = tid; idx < 64 * 16; idx += 256) {
        int r = idx >> 4, d4 = idx & 15;
        float4 v4 = *(const float4*)&qp[(size_t)(q0 + r) * DD + d4 * 4];
        Qt[(d4 * 4 + 0) * STR + r] = v4.x;
        Qt[(d4 * 4 + 1) * STR + r] = v4.y;
        Qt[(d4 * 4 + 2) * STR + r] = v4.z;
        Qt[(d4 * 4 + 3) * STR + r] = v4.w;
    }
    if (tid < 64) { m_row[tid] = -1e30f; l_row[tid] = 0.f; }
    float O[4][4] = {};
    __syncthreads();

    for (int kt = 0; kt <= qtile; kt++) {
        const int k0 = kt * 64;
        // Load K (transposed) and V tiles
        for (int idx = tid; idx < 64 * 16; idx += 256) {
            int c = idx >> 4, d4 = idx & 15;
            float4 v4 = *(const float4*)&kp[(size_t)(k0 + c) * DD + d4 * 4];
            Kt[(d4 * 4 + 0) * STR + c] = v4.x;
            Kt[(d4 * 4 + 1) * STR + c] = v4.y;
            Kt[(d4 * 4 + 2) * STR + c] = v4.z;
            Kt[(d4 * 4 + 3) * STR + c] = v4.w;
            float4 w4 = *(const float4*)&vp[(size_t)(k0 + c) * DD + d4 * 4];
            *(float4*)&Vs[c * STR + d4 * 4] = w4;
        }
        __syncthreads();

        // S = Q K^T (register GEMM over d)
        float acc[4][4] = {};
        #pragma unroll 8
        for (int d = 0; d < 64; d++) {
            float4 a = *(float4*)&Qt[d * STR + ty * 4];
            float4 bv = *(float4*)&Kt[d * STR + tx * 4];
            float ar[4] = {a.x, a.y, a.z, a.w};
            float br[4] = {bv.x, bv.y, bv.z, bv.w};
            #pragma unroll
            for (int i = 0; i < 4; i++)
                #pragma unroll
                for (int j = 0; j < 4; j++)
                    acc[i][j] += ar[i] * br[j];
        }
        // scale + ALiBi + causal mask, store to smem
        #pragma unroll
        for (int i = 0; i < 4; i++) {
            int r = ty * 4 + i;
            #pragma unroll
            for (int j = 0; j < 4; j++) {
                int c = tx * 4 + j;
                float s = acc[i][j] * scale
                        + slope * (float)((k0 + c) - (q0 + r));
                if (k0 + c > q0 + r) s = -1e30f;
                Ss[r * STR + c] = s;
            }
        }
        __syncthreads();

        // Online softmax: one thread per row
        if (tid < 64) {
            int r = tid;
            float mprev = m_row[r];
            float tmax = -1e30f;
            #pragma unroll 8
            for (int j = 0; j < 64; j++) tmax = fmaxf(tmax, Ss[r * STR + j]);
            float mnew = fmaxf(mprev, tmax);
            float corr = __expf(mprev - mnew);
            float rs = 0.f;
            #pragma unroll 8
            for (int j = 0; j < 64; j++) {
                float p = __expf(Ss[r * STR + j] - mnew);
                Ss[r * STR + j] = p;
                rs += p;
            }
            l_row[r] = l_row[r] * corr + rs;
            m_row[r] = mnew;
            c_row[r] = corr;
        }
        __syncthreads();

        // Rescale running O, then O += P @ V
        float cr[4];
        #pragma unroll
        for (int i = 0; i < 4; i++) {
            cr[i] = c_row[ty * 4 + i];
            #pragma unroll
            for (int j = 0; j < 4; j++) O[i][j] *= cr[i];
        }
        #pragma unroll 8
        for (int c = 0; c < 64; c++) {
            float4 bv = *(float4*)&Vs[c * STR + tx * 4];
            float br[4] = {bv.x, bv.y, bv.z, bv.w};
            float ar[4];
            #pragma unroll
            for (int i = 0; i < 4; i++) ar[i] = Ss[(ty * 4 + i) * STR + c];
            #pragma unroll
            for (int i = 0; i < 4; i++)
                #pragma unroll
                for (int j = 0; j < 4; j++)
                    O[i][j] += ar[i] * br[j];
        }
        __syncthreads();   // protect Kt/Vs/Ss before next tile's loads
    }

    // Epilogue: normalize and write y[b, q, h, d]
    #pragma unroll
    for (int i = 0; i < 4; i++) {
        int r = ty * 4 + i;
        float inv = 1.f / l_row[r];
        float4 o4 = make_float4(O[i][0] * inv, O[i][1] * inv,
                                O[i][2] * inv, O[i][3] * inv);
        *(float4*)&g_y[(((size_t)(b * TT + q0 + r) * HH) + h) * DD + tx * 4] = o4;
    }
}

// ---------------------------------------------------------------------------
// Kernel 4: out[b,t,i*64+d] = sum_j y[b,t,j,d] * proj_tmp[i][j]
// ---------------------------------------------------------------------------
__global__ __launch_bounds__(256) void proj_kernel(
    const float* __restrict__ proj_tmp, float* __restrict__ out)
{
    __shared__ float ys[CC];
    __shared__ float wt[HH * HH];
    const int bt  = blockIdx.x;
    const int tid = threadIdx.x;
    wt[tid] = proj_tmp[tid];
    #pragma unroll
    for (int i = tid; i < CC; i += 256) ys[i] = g_y[(size_t)bt * CC + i];
    __syncthreads();
    for (int o = tid; o < CC; o += 256) {
        int i = o >> 6, d = o & 63;
        float s = 0.f;
        #pragma unroll
        for (int j = 0; j < HH; j++) s += ys[j * DD + d] * wt[i * HH + j];
        out[(size_t)bt * CC + o] = s;
    }
}

// ---------------------------------------------------------------------------
extern "C" void kernel_launch(void* const* d_in, const int* in_sizes, int n_in,
                              void* d_out, int out_size)
{
    const float* x     = (const float*)d_in[0];
    const float* W     = (const float*)d_in[1];
    const float* v_tmp = (const float*)d_in[2];
    const float* p_tmp = (const float*)d_in[3];
    float* out = (float*)d_out;
    (void)in_sizes; (void)n_in; (void)out_size;

    gemm_qk_kernel<<<dim3(32, 64), 256>>>(x, W);
    vmix_kernel<<<BT, 256>>>(x, v_tmp);

    size_t smem = (size_t)(4 * 64 * STR + 3 * 64) * sizeof(float); // ~70.4 KB
    cudaFuncSetAttribute(attn_kernel,
                         cudaFuncAttributeMaxDynamicSharedMemorySize, (int)smem);
    attn_kernel<<<dim3(TT / 64, BH), 256, smem>>>();

    proj_kernel<<<BT, 256>>>(p_tmp, out);
}

// round 5
// speedup vs baseline: 2.7180x; 2.7180x over previous
#include <cuda_runtime.h>
#include <math.h>
#include <stdint.h>

// Problem constants
#define BB 2
#define TT 2048
#define HH 16
#define DD 64
#define CC 1024          // HH*DD
#define BT (BB*TT)       // 4096
#define BH (BB*HH)       // 32

// Scratch (no allocation allowed)
__device__ float g_q[BH * TT * DD];      // [b,h,t,d]
__device__ float g_k[BH * TT * DD];      // [b,h,t,d]
__device__ float g_v[BH * TT * DD];      // [b,h,t,d]  (head-mixed V)
__device__ float g_y[BB * TT * HH * DD]; // [b,t,h,d]

// ---------------------------------------------------------------------------
// tf32 helpers
// ---------------------------------------------------------------------------
__device__ __forceinline__ uint32_t f2tf32(float f) {
    uint32_t u;
    asm("cvt.rna.tf32.f32 %0, %1;" : "=r"(u) : "f"(f));
    return u;
}

__device__ __forceinline__ void mma_tf32(float (&c)[4],
    uint32_t a0, uint32_t a1, uint32_t a2, uint32_t a3,
    uint32_t b0, uint32_t b1)
{
    asm volatile(
        "mma.sync.aligned.m16n8k8.row.col.f32.tf32.tf32.f32 "
        "{%0,%1,%2,%3}, {%4,%5,%6,%7}, {%8,%9}, {%0,%1,%2,%3};\n"
        : "+f"(c[0]), "+f"(c[1]), "+f"(c[2]), "+f"(c[3])
        : "r"(a0), "r"(a1), "r"(a2), "r"(a3), "r"(b0), "r"(b1));
}

// ---------------------------------------------------------------------------
// Kernel 1: qk = x @ W_attn  (tf32 mma). 128x128 block tile, BK=32,
// 8 warps in 2(m) x 4(n), each warp 64x32. Splits result into q/k, [b,h,t,d].
// ---------------------------------------------------------------------------
#define ASTR 36
#define BSTR 132

__global__ __launch_bounds__(256) void gemm_qk_mma(
    const float* __restrict__ x, const float* __restrict__ W)
{
    __shared__ float As[128 * ASTR];
    __shared__ float Bs[32 * BSTR];

    const int tid  = threadIdx.x;
    const int lane = tid & 31;
    const int w    = tid >> 5;
    const int wm   = w & 1;      // 2 m-warps (64 rows each)
    const int wn   = w >> 1;     // 4 n-warps (32 cols each)
    const int g    = lane >> 2;  // 0..7
    const int t4   = lane & 3;   // 0..3

    const int m0 = blockIdx.y * 128;
    const int n0 = blockIdx.x * 128;

    // gmem tile loaders
    const int ar  = tid >> 3;    // 0..31 (A row base, 4 passes of +32)
    const int ac4 = tid & 7;     // A float4 col (k)
    const int br  = tid >> 3;    // 0..31 (B row = k)
    const int bc4 = tid & 7;     // B float4 col base (4 passes of +8)

    float acc[4][4][4] = {};

    for (int k0 = 0; k0 < CC; k0 += 32) {
        float4 av[4], bv[4];
        #pragma unroll
        for (int p = 0; p < 4; p++)
            av[p] = *(const float4*)&x[(size_t)(m0 + ar + p * 32) * CC + k0 + ac4 * 4];
        #pragma unroll
        for (int p = 0; p < 4; p++)
            bv[p] = *(const float4*)&W[(size_t)(k0 + br) * (2 * CC) + n0 + (bc4 + p * 8) * 4];

        __syncthreads();
        #pragma unroll
        for (int p = 0; p < 4; p++) {
            float* d = &As[(ar + p * 32) * ASTR + ac4 * 4];
            d[0] = __uint_as_float(f2tf32(av[p].x));
            d[1] = __uint_as_float(f2tf32(av[p].y));
            d[2] = __uint_as_float(f2tf32(av[p].z));
            d[3] = __uint_as_float(f2tf32(av[p].w));
        }
        #pragma unroll
        for (int p = 0; p < 4; p++) {
            float* d = &Bs[br * BSTR + (bc4 + p * 8) * 4];
            d[0] = __uint_as_float(f2tf32(bv[p].x));
            d[1] = __uint_as_float(f2tf32(bv[p].y));
            d[2] = __uint_as_float(f2tf32(bv[p].z));
            d[3] = __uint_as_float(f2tf32(bv[p].w));
        }
        __syncthreads();

        #pragma unroll
        for (int kk = 0; kk < 4; kk++) {
            uint32_t af[4][4], bf[4][2];
            #pragma unroll
            for (int mt = 0; mt < 4; mt++) {
                int mrow = wm * 64 + mt * 16;
                af[mt][0] = __float_as_uint(As[(mrow + g) * ASTR + kk * 8 + t4]);
                af[mt][1] = __float_as_uint(As[(mrow + 8 + g) * ASTR + kk * 8 + t4]);
                af[mt][2] = __float_as_uint(As[(mrow + g) * ASTR + kk * 8 + t4 + 4]);
                af[mt][3] = __float_as_uint(As[(mrow + 8 + g) * ASTR + kk * 8 + t4 + 4]);
            }
            #pragma unroll
            for (int nt = 0; nt < 4; nt++) {
                int ncol = wn * 32 + nt * 8 + g;
                bf[nt][0] = __float_as_uint(Bs[(kk * 8 + t4) * BSTR + ncol]);
                bf[nt][1] = __float_as_uint(Bs[(kk * 8 + t4 + 4) * BSTR + ncol]);
            }
            #pragma unroll
            for (int mt = 0; mt < 4; mt++)
                #pragma unroll
                for (int nt = 0; nt < 4; nt++)
                    mma_tf32(acc[mt][nt], af[mt][0], af[mt][1], af[mt][2], af[mt][3],
                             bf[nt][0], bf[nt][1]);
        }
    }

    // Epilogue: scatter into g_q/g_k [b,h,t,d]
    #pragma unroll
    for (int mt = 0; mt < 4; mt++) {
        #pragma unroll
        for (int nt = 0; nt < 4; nt++) {
            #pragma unroll
            for (int half = 0; half < 2; half++) {
                int row  = m0 + wm * 64 + mt * 16 + g + half * 8;
                int ncol = n0 + wn * 32 + nt * 8 + 2 * t4;
                int b = row >> 11;
                int t = row & (TT - 1);
                bool isq = (ncol < CC);
                int hh = (ncol >> 6) & (HH - 1);
                int dd = ncol & 63;
                float* dst = isq ? g_q : g_k;
                float2 v2 = make_float2(acc[mt][nt][half * 2], acc[mt][nt][half * 2 + 1]);
                *(float2*)&dst[(((size_t)(b * HH + hh) * TT) + t) * DD + dd] = v2;
            }
        }
    }
}

// ---------------------------------------------------------------------------
// Kernel 2: v[b,j,t,d] = sum_i x[b,t,i*64+d] * v_tmp[i][j]   (head mixing)
// ---------------------------------------------------------------------------
__global__ __launch_bounds__(256) void vmix_kernel(
    const float* __restrict__ x, const float* __restrict__ v_tmp)
{
    __shared__ float xs[CC];
    __shared__ float wt[HH * HH];
    const int bt  = blockIdx.x;
    const int tid = threadIdx.x;
    wt[tid] = v_tmp[tid];
    #pragma unroll
    for (int i = tid; i < CC; i += 256) xs[i] = x[(size_t)bt * CC + i];
    __syncthreads();
    const int b = bt >> 11;
    const int t = bt & (TT - 1);
    for (int o = tid; o < CC; o += 256) {
        int j = o >> 6, d = o & 63;
        float s = 0.f;
        #pragma unroll
        for (int i = 0; i < HH; i++) s += xs[i * DD + d] * wt[i * HH + j];
        g_v[(((size_t)(b * HH + j) * TT) + t) * DD + d] = s;
    }
}

// ---------------------------------------------------------------------------
// Kernel 3: flash-attention, tf32 mma. Q-tile 128 rows x (b,h). 8 warps,
// each warp owns 16 q-rows, full 64-col KV tile. Q fragments register-
// resident for the entire KV loop. P goes through per-warp smem to convert
// C-fragment layout -> A-fragment layout for P@V.
// ---------------------------------------------------------------------------
#define KSTR 68
#define PSTR 68

__global__ __launch_bounds__(256) void attn_mma()
{
    extern __shared__ float sm[];
    float* Ks = sm;                    // [64][KSTR]  (tf32 bits)
    float* Vs = Ks + 64 * KSTR;        // [64][KSTR]
    float* Ps = Vs + 64 * KSTR;        // 8 warps x [16][PSTR]

    const int tid  = threadIdx.x;
    const int lane = tid & 31;
    const int w    = tid >> 5;
    const int g    = lane >> 2;
    const int t4   = lane & 3;
    const int qt   = blockIdx.x;
    const int bh   = blockIdx.y;
    const int h    = bh & (HH - 1);
    const int b    = bh >> 4;
    const int q0   = qt * 128;

    const float* qp = g_q + (size_t)bh * TT * DD;
    const float* kp = g_k + (size_t)bh * TT * DD;
    const float* vp = g_v + (size_t)bh * TT * DD;

    const float slope = exp2f(-0.5f * (float)(h + 1));

    // Q fragments (scale folded in), resident for the whole loop
    uint32_t qa[8][4];
    const int qrow = q0 + w * 16;
    #pragma unroll
    for (int kk = 0; kk < 8; kk++) {
        qa[kk][0] = f2tf32(0.125f * qp[(size_t)(qrow + g) * DD + kk * 8 + t4]);
        qa[kk][1] = f2tf32(0.125f * qp[(size_t)(qrow + 8 + g) * DD + kk * 8 + t4]);
        qa[kk][2] = f2tf32(0.125f * qp[(size_t)(qrow + g) * DD + kk * 8 + t4 + 4]);
        qa[kk][3] = f2tf32(0.125f * qp[(size_t)(qrow + 8 + g) * DD + kk * 8 + t4 + 4]);
    }

    float oc[8][4] = {};
    float m0r = -1e30f, m1r = -1e30f, l0r = 0.f, l1r = 0.f;
    float* Pw = Ps + w * 16 * PSTR;

    const int r0 = q0 + w * 16 + g;
    const int r1 = r0 + 8;
    const int ktmax = 2 * qt + 1;

    for (int kt = 0; kt <= ktmax; kt++) {
        const int k0 = kt * 64;
        __syncthreads();   // prior iteration's Ks/Vs reads complete
        // Load K,V tiles (cvt to tf32 once, in the fill path)
        #pragma unroll
        for (int p = 0; p < 4; p++) {
            int idx = tid + p * 256;          // 0..1023
            int r  = idx >> 4;
            int c4 = idx & 15;
            float4 k4 = *(const float4*)&kp[(size_t)(k0 + r) * DD + c4 * 4];
            float* dk = &Ks[r * KSTR + c4 * 4];
            dk[0] = __uint_as_float(f2tf32(k4.x));
            dk[1] = __uint_as_float(f2tf32(k4.y));
            dk[2] = __uint_as_float(f2tf32(k4.z));
            dk[3] = __uint_as_float(f2tf32(k4.w));
            float4 v4 = *(const float4*)&vp[(size_t)(k0 + r) * DD + c4 * 4];
            float* dv = &Vs[r * KSTR + c4 * 4];
            dv[0] = __uint_as_float(f2tf32(v4.x));
            dv[1] = __uint_as_float(f2tf32(v4.y));
            dv[2] = __uint_as_float(f2tf32(v4.z));
            dv[3] = __uint_as_float(f2tf32(v4.w));
        }
        __syncthreads();

        // S = Q K^T
        float sc[8][4] = {};
        #pragma unroll
        for (int kk = 0; kk < 8; kk++) {
            uint32_t bf[8][2];
            #pragma unroll
            for (int nt = 0; nt < 8; nt++) {
                bf[nt][0] = __float_as_uint(Ks[(nt * 8 + g) * KSTR + kk * 8 + t4]);
                bf[nt][1] = __float_as_uint(Ks[(nt * 8 + g) * KSTR + kk * 8 + t4 + 4]);
            }
            #pragma unroll
            for (int nt = 0; nt < 8; nt++)
                mma_tf32(sc[nt], qa[kk][0], qa[kk][1], qa[kk][2], qa[kk][3],
                         bf[nt][0], bf[nt][1]);
        }

        // ALiBi + causal mask + online softmax
        float mx0 = -1e30f, mx1 = -1e30f;
        #pragma unroll
        for (int nt = 0; nt < 8; nt++) {
            #pragma unroll
            for (int e = 0; e < 4; e++) {
                int col = k0 + nt * 8 + 2 * t4 + (e & 1);
                int row = (e < 2) ? r0 : r1;
                float s = sc[nt][e] + slope * (float)(col - row);
                if (col > row) s = -1e30f;
                sc[nt][e] = s;
            }
            mx0 = fmaxf(mx0, fmaxf(sc[nt][0], sc[nt][1]));
            mx1 = fmaxf(mx1, fmaxf(sc[nt][2], sc[nt][3]));
        }
        mx0 = fmaxf(mx0, __shfl_xor_sync(0xffffffffu, mx0, 1));
        mx0 = fmaxf(mx0, __shfl_xor_sync(0xffffffffu, mx0, 2));
        mx1 = fmaxf(mx1, __shfl_xor_sync(0xffffffffu, mx1, 1));
        mx1 = fmaxf(mx1, __shfl_xor_sync(0xffffffffu, mx1, 2));
        float mn0 = fmaxf(m0r, mx0), mn1 = fmaxf(m1r, mx1);
        float corr0 = __expf(m0r - mn0), corr1 = __expf(m1r - mn1);

        float rs0 = 0.f, rs1 = 0.f;
        #pragma unroll
        for (int nt = 0; nt < 8; nt++) {
            float p0 = __expf(sc[nt][0] - mn0);
            float p1 = __expf(sc[nt][1] - mn0);
            float p2 = __expf(sc[nt][2] - mn1);
            float p3 = __expf(sc[nt][3] - mn1);
            rs0 += p0 + p1;
            rs1 += p2 + p3;
            *(float2*)&Pw[g * PSTR + nt * 8 + 2 * t4] =
                make_float2(__uint_as_float(f2tf32(p0)), __uint_as_float(f2tf32(p1)));
            *(float2*)&Pw[(g + 8) * PSTR + nt * 8 + 2 * t4] =
                make_float2(__uint_as_float(f2tf32(p2)), __uint_as_float(f2tf32(p3)));
        }
        rs0 += __shfl_xor_sync(0xffffffffu, rs0, 1);
        rs0 += __shfl_xor_sync(0xffffffffu, rs0, 2);
        rs1 += __shfl_xor_sync(0xffffffffu, rs1, 1);
        rs1 += __shfl_xor_sync(0xffffffffu, rs1, 2);
        m0r = mn0; m1r = mn1;
        l0r = l0r * corr0 + rs0;
        l1r = l1r * corr1 + rs1;

        // rescale running O
        #pragma unroll
        for (int nt = 0; nt < 8; nt++) {
            oc[nt][0] *= corr0; oc[nt][1] *= corr0;
            oc[nt][2] *= corr1; oc[nt][3] *= corr1;
        }
        __syncwarp();   // Pw writes visible across the warp

        // O += P @ V
        #pragma unroll
        for (int kk = 0; kk < 8; kk++) {
            uint32_t a0 = __float_as_uint(Pw[g * PSTR + kk * 8 + t4]);
            uint32_t a1 = __float_as_uint(Pw[(g + 8) * PSTR + kk * 8 + t4]);
            uint32_t a2 = __float_as_uint(Pw[g * PSTR + kk * 8 + t4 + 4]);
            uint32_t a3 = __float_as_uint(Pw[(g + 8) * PSTR + kk * 8 + t4 + 4]);
            #pragma unroll
            for (int nt = 0; nt < 8; nt++) {
                uint32_t b0 = __float_as_uint(Vs[(kk * 8 + t4) * KSTR + nt * 8 + g]);
                uint32_t b1 = __float_as_uint(Vs[(kk * 8 + t4 + 4) * KSTR + nt * 8 + g]);
                mma_tf32(oc[nt], a0, a1, a2, a3, b0, b1);
            }
        }
        __syncwarp();   // Pw reads done before next iteration's writes
    }

    // Epilogue: normalize and write y[b, t, h, d]
    float inv0 = 1.f / l0r, inv1 = 1.f / l1r;
    #pragma unroll
    for (int nt = 0; nt < 8; nt++) {
        int d = nt * 8 + 2 * t4;
        *(float2*)&g_y[(((size_t)(b * TT + r0) * HH) + h) * DD + d] =
            make_float2(oc[nt][0] * inv0, oc[nt][1] * inv0);
        *(float2*)&g_y[(((size_t)(b * TT + r1) * HH) + h) * DD + d] =
            make_float2(oc[nt][2] * inv1, oc[nt][3] * inv1);
    }
}

// ---------------------------------------------------------------------------
// Kernel 4: out[b,t,i*64+d] = sum_j y[b,t,j,d] * proj_tmp[i][j]
// ---------------------------------------------------------------------------
__global__ __launch_bounds__(256) void proj_kernel(
    const float* __restrict__ proj_tmp, float* __restrict__ out)
{
    __shared__ float ys[CC];
    __shared__ float wt[HH * HH];
    const int bt  = blockIdx.x;
    const int tid = threadIdx.x;
    wt[tid] = proj_tmp[tid];
    #pragma unroll
    for (int i = tid; i < CC; i += 256) ys[i] = g_y[(size_t)bt * CC + i];
    __syncthreads();
    for (int o = tid; o < CC; o += 256) {
        int i = o >> 6, d = o & 63;
        float s = 0.f;
        #pragma unroll
        for (int j = 0; j < HH; j++) s += ys[j * DD + d] * wt[i * HH + j];
        out[(size_t)bt * CC + o] = s;
    }
}

// ---------------------------------------------------------------------------
extern "C" void kernel_launch(void* const* d_in, const int* in_sizes, int n_in,
                              void* d_out, int out_size)
{
    const float* x     = (const float*)d_in[0];
    const float* W     = (const float*)d_in[1];
    const float* v_tmp = (const float*)d_in[2];
    const float* p_tmp = (const float*)d_in[3];
    float* out = (float*)d_out;
    (void)in_sizes; (void)n_in; (void)out_size;

    gemm_qk_mma<<<dim3(2 * CC / 128, BT / 128), 256>>>(x, W);
    vmix_kernel<<<BT, 256>>>(x, v_tmp);

    size_t smem = (size_t)(2 * 64 * KSTR + 8 * 16 * PSTR) * sizeof(float); // ~68 KB
    cudaFuncSetAttribute(attn_mma,
                         cudaFuncAttributeMaxDynamicSharedMemorySize, (int)smem);
    attn_mma<<<dim3(TT / 128, BH), 256, smem>>>();

    proj_kernel<<<BT, 256>>>(p_tmp, out);
}

// round 7
// speedup vs baseline: 2.8837x; 1.0610x over previous
#include <cuda_runtime.h>
#include <math.h>
#include <stdint.h>

// Problem constants
#define BB 2
#define TT 2048
#define HH 16
#define DD 64
#define CC 1024          // HH*DD
#define BT (BB*TT)       // 4096
#define BH (BB*HH)       // 32

// Scratch (no allocation allowed)
__device__ float g_xr[BT * CC];          // tf32-rounded x
__device__ float g_wr[CC * 2 * CC];      // tf32-rounded W_attn
__device__ float g_q[BH * TT * DD];      // [b,h,t,d] fp32
__device__ float g_k[BH * TT * DD];      // [b,h,t,d] tf32-rounded
__device__ float g_v[BH * TT * DD];      // [b,h,t,d] fp32 (head-mixed V)
__device__ float g_vt[BH * DD * TT];     // [b,h,d,t] tf32-rounded (transposed V)
__device__ float g_y[BB * TT * HH * DD]; // [b,t,h,d]

// ---------------------------------------------------------------------------
// helpers
// ---------------------------------------------------------------------------
__device__ __forceinline__ uint32_t f2tf32(float f) {
    uint32_t u;
    asm("cvt.rna.tf32.f32 %0, %1;" : "=r"(u) : "f"(f));
    return u;
}
__device__ __forceinline__ float rtf(float f) { return __uint_as_float(f2tf32(f)); }

__device__ __forceinline__ void mma_tf32(float (&c)[4],
    uint32_t a0, uint32_t a1, uint32_t a2, uint32_t a3,
    uint32_t b0, uint32_t b1)
{
    asm volatile(
        "mma.sync.aligned.m16n8k8.row.col.f32.tf32.tf32.f32 "
        "{%0,%1,%2,%3}, {%4,%5,%6,%7}, {%8,%9}, {%0,%1,%2,%3};\n"
        : "+f"(c[0]), "+f"(c[1]), "+f"(c[2]), "+f"(c[3])
        : "r"(a0), "r"(a1), "r"(a2), "r"(a3), "r"(b0), "r"(b1));
}

__device__ __forceinline__ void cpa16(uint32_t dst, const void* src) {
    asm volatile("cp.async.cg.shared.global [%0], [%1], 16;\n" :: "r"(dst), "l"(src));
}
#define CP_COMMIT() asm volatile("cp.async.commit_group;\n" ::: "memory")
#define CP_WAIT0()  asm volatile("cp.async.wait_group 0;\n" ::: "memory")

// ---------------------------------------------------------------------------
// Kernel 0: pre-round x and W to tf32 (rna) so cp.async raw copies keep
// round-to-nearest precision in the mma kernels.
// ---------------------------------------------------------------------------
__global__ __launch_bounds__(256) void preround(
    const float* __restrict__ x, const float* __restrict__ W)
{
    int i = blockIdx.x * blockDim.x + threadIdx.x;
    int stride = gridDim.x * blockDim.x;
    const float4* x4 = (const float4*)x;
    const float4* w4 = (const float4*)W;
    float4* xo = (float4*)g_xr;
    float4* wo = (float4*)g_wr;
    for (int j = i; j < BT * CC / 4; j += stride) {
        float4 v = x4[j];
        xo[j] = make_float4(rtf(v.x), rtf(v.y), rtf(v.z), rtf(v.w));
    }
    for (int j = i; j < CC * 2 * CC / 4; j += stride) {
        float4 v = w4[j];
        wo[j] = make_float4(rtf(v.x), rtf(v.y), rtf(v.z), rtf(v.w));
    }
}

// ---------------------------------------------------------------------------
// Kernel 1: qk = x @ W_attn (tf32 mma, cp.async double-buffered).
// 128x128 tile, BK=32. A smem [m][k] natural, B smem [k][n] natural.
// k-slot permutation: mma k-slot t4 -> physical k = 2*t4 (slot t4+4 -> 2*t4+1)
// so A-frag pairs are float2 and B-frag rows are adjacent (conflict-free).
// ---------------------------------------------------------------------------
#define GA_STR 36
#define GB_STR 132
#define GA_SZ (128 * GA_STR)
#define GB_SZ (32 * GB_STR)

__global__ __launch_bounds__(256, 2) void gemm_qk_mma()
{
    extern __shared__ float sm[];
    const int tid  = threadIdx.x;
    const int lane = tid & 31;
    const int w    = tid >> 5;
    const int wm   = w & 1;       // 2 m-warps (64 rows)
    const int wn   = w >> 1;      // 4 n-warps (32 cols)
    const int g    = lane >> 2;
    const int t4   = lane & 3;
    const int m0 = blockIdx.y * 128;
    const int n0 = blockIdx.x * 128;
    const uint32_t sbase = (uint32_t)__cvta_generic_to_shared(sm);

    auto load_tiles = [&](int buf, int k0) {
        #pragma unroll
        for (int p = 0; p < 4; p++) {               // A: 128x32 fp32
            int id = tid + p * 256;
            int r = id >> 3, c = id & 7;
            cpa16(sbase + (uint32_t)(buf * GA_SZ + r * GA_STR + c * 4) * 4,
                  &g_xr[(size_t)(m0 + r) * CC + k0 + c * 4]);
        }
        #pragma unroll
        for (int p = 0; p < 4; p++) {               // B: 32x128 fp32
            int id = tid + p * 256;
            int r = id >> 5, c = id & 31;
            cpa16(sbase + (uint32_t)(2 * GA_SZ + buf * GB_SZ + r * GB_STR + c * 4) * 4,
                  &g_wr[(size_t)(k0 + r) * (2 * CC) + n0 + c * 4]);
        }
    };

    float acc[4][4][4] = {};
    load_tiles(0, 0); CP_COMMIT();
    int buf = 0;
    for (int it = 0; it < 32; it++) {
        CP_WAIT0();
        __syncthreads();
        if (it < 31) { load_tiles(buf ^ 1, (it + 1) * 32); CP_COMMIT(); }
        const float* A = sm + buf * GA_SZ;
        const float* B = sm + 2 * GA_SZ + buf * GB_SZ;

        #pragma unroll
        for (int kk = 0; kk < 4; kk++) {
            float2 aL[4], aH[4];
            #pragma unroll
            for (int mt = 0; mt < 4; mt++) {
                int row = wm * 64 + mt * 16 + g;
                aL[mt] = *(const float2*)&A[row * GA_STR + kk * 8 + 2 * t4];
                aH[mt] = *(const float2*)&A[(row + 8) * GA_STR + kk * 8 + 2 * t4];
            }
            float b0[4], b1[4];
            #pragma unroll
            for (int nt = 0; nt < 4; nt++) {
                int col = wn * 32 + nt * 8 + g;
                b0[nt] = B[(kk * 8 + 2 * t4) * GB_STR + col];
                b1[nt] = B[(kk * 8 + 2 * t4 + 1) * GB_STR + col];
            }
            #pragma unroll
            for (int mt = 0; mt < 4; mt++)
                #pragma unroll
                for (int nt = 0; nt < 4; nt++)
                    mma_tf32(acc[mt][nt],
                             __float_as_uint(aL[mt].x), __float_as_uint(aH[mt].x),
                             __float_as_uint(aL[mt].y), __float_as_uint(aH[mt].y),
                             __float_as_uint(b0[nt]),   __float_as_uint(b1[nt]));
        }
        buf ^= 1;
    }

    // Epilogue: scatter into g_q/g_k [b,h,t,d], tf32-rounded (consumed raw by attn)
    #pragma unroll
    for (int mt = 0; mt < 4; mt++) {
        #pragma unroll
        for (int nt = 0; nt < 4; nt++) {
            #pragma unroll
            for (int half = 0; half < 2; half++) {
                int row  = m0 + wm * 64 + mt * 16 + g + half * 8;
                int ncol = n0 + wn * 32 + nt * 8 + 2 * t4;
                int b = row >> 11;
                int t = row & (TT - 1);
                bool isq = (ncol < CC);
                int hh = (ncol >> 6) & (HH - 1);
                int dd = ncol & 63;
                float* dst = isq ? g_q : g_k;
                float2 v2 = make_float2(rtf(acc[mt][nt][half * 2]),
                                        rtf(acc[mt][nt][half * 2 + 1]));
                *(float2*)&dst[(((size_t)(b * HH + hh) * TT) + t) * DD + dd] = v2;
            }
        }
    }
}

// ---------------------------------------------------------------------------
// Kernel 2: v[b,j,t,d] = sum_i x[b,t,i*64+d] * v_tmp[i][j]   (head mixing)
// ---------------------------------------------------------------------------
__global__ __launch_bounds__(256) void vmix_kernel(
    const float* __restrict__ x, const float* __restrict__ v_tmp)
{
    __shared__ float xs[CC];
    __shared__ float wt[HH * HH];
    const int bt  = blockIdx.x;
    const int tid = threadIdx.x;
    wt[tid] = v_tmp[tid];
    #pragma unroll
    for (int i = tid; i < CC; i += 256) xs[i] = x[(size_t)bt * CC + i];
    __syncthreads();
    const int b = bt >> 11;
    const int t = bt & (TT - 1);
    for (int o = tid; o < CC; o += 256) {
        int j = o >> 6, d = o & 63;
        float s = 0.f;
        #pragma unroll
        for (int i = 0; i < HH; i++) s += xs[i * DD + d] * wt[i * HH + j];
        g_v[(((size_t)(b * HH + j) * TT) + t) * DD + d] = s;
    }
}

// ---------------------------------------------------------------------------
// Kernel 2b: transpose V to [b,h,d,t] (tf32-rounded) so attention's PV k-dim
// (tokens) is contiguous for float2 b-fragments + cp.async.
// ---------------------------------------------------------------------------
__global__ __launch_bounds__(256) void vtrans_kernel()
{
    __shared__ float ts[64][65];
    const int bh = blockIdx.y;
    const int t0 = blockIdx.x * 64;
    const float* src = g_v + (size_t)bh * TT * DD;
    float* dst = g_vt + (size_t)bh * DD * TT;
    const int r  = threadIdx.x >> 4;
    const int c4 = threadIdx.x & 15;
    #pragma unroll
    for (int p = 0; p < 4; p++) {
        float4 v = *(const float4*)&src[(size_t)(t0 + r + p * 16) * DD + c4 * 4];
        ts[r + p * 16][c4 * 4 + 0] = v.x;
        ts[r + p * 16][c4 * 4 + 1] = v.y;
        ts[r + p * 16][c4 * 4 + 2] = v.z;
        ts[r + p * 16][c4 * 4 + 3] = v.w;
    }
    __syncthreads();
    #pragma unroll
    for (int p = 0; p < 4; p++) {
        int d = r + p * 16;
        float4 o = make_float4(rtf(ts[c4 * 4 + 0][d]), rtf(ts[c4 * 4 + 1][d]),
                               rtf(ts[c4 * 4 + 2][d]), rtf(ts[c4 * 4 + 3][d]));
        *(float4*)&dst[(size_t)d * TT + t0 + c4 * 4] = o;
    }
}

// ---------------------------------------------------------------------------
// Kernel 3: flash-attention, tf32 mma, cp.async double-buffered K/V.
// Q-tile 128 x (b,h); 8 warps x 16 q-rows. k-slot permutation makes:
//  - K b-frags one float2 each from natural Ks[c][d]
//  - V b-frags one float2 each from natural Vst[d][t] (g_vt)
//  - softmax'd S C-fragment consumable DIRECTLY as P A-fragment (no smem P!)
// ---------------------------------------------------------------------------
#define AT_STR 68
#define AT_SZ  (64 * AT_STR)

__global__ __launch_bounds__(256, 2) void attn_mma()
{
    extern __shared__ float sm[];
    const int tid  = threadIdx.x;
    const int lane = tid & 31;
    const int w    = tid >> 5;
    const int g    = lane >> 2;
    const int t4   = lane & 3;
    const int qt   = blockIdx.x;
    const int bh   = blockIdx.y;
    const int h    = bh & (HH - 1);
    const int b    = bh >> 4;
    const int q0   = qt * 128;

    const float* qp  = g_q  + (size_t)bh * TT * DD;
    const float* kp  = g_k  + (size_t)bh * TT * DD;
    const float* vtp = g_vt + (size_t)bh * DD * TT;
    const uint32_t sbase = (uint32_t)__cvta_generic_to_shared(sm);

    const float slope = exp2f(-0.5f * (float)(h + 1));

    // Q fragments (scale folded, rna). k-slot t4 -> phys d 2*t4 (+1 for slot t4+4)
    uint32_t qa[8][4];
    const int qrow = q0 + w * 16;
    #pragma unroll
    for (int kk = 0; kk < 8; kk++) {
        float2 lo = *(const float2*)&qp[(size_t)(qrow + g) * DD + kk * 8 + 2 * t4];
        float2 hi = *(const float2*)&qp[(size_t)(qrow + 8 + g) * DD + kk * 8 + 2 * t4];
        qa[kk][0] = f2tf32(0.125f * lo.x);
        qa[kk][1] = f2tf32(0.125f * hi.x);
        qa[kk][2] = f2tf32(0.125f * lo.y);
        qa[kk][3] = f2tf32(0.125f * hi.y);
    }

    auto load_kv = [&](int buf, int k0) {
        #pragma unroll
        for (int p = 0; p < 4; p++) {                 // K: 64 tokens x 64 d
            int id = tid + p * 256;
            int r = id >> 4, c = id & 15;
            cpa16(sbase + (uint32_t)(buf * AT_SZ + r * AT_STR + c * 4) * 4,
                  &kp[(size_t)(k0 + r) * DD + c * 4]);
        }
        #pragma unroll
        for (int p = 0; p < 4; p++) {                 // V^T: 64 d x 64 tokens
            int id = tid + p * 256;
            int r = id >> 4, c = id & 15;
            cpa16(sbase + (uint32_t)((2 + buf) * AT_SZ + r * AT_STR + c * 4) * 4,
                  &vtp[(size_t)r * TT + k0 + c * 4]);
        }
    };

    float oc[8][4] = {};
    float m0r = -1e30f, m1r = -1e30f, l0r = 0.f, l1r = 0.f;
    const int r0 = qrow + g;
    const int r1 = r0 + 8;
    const int ktmax = 2 * qt + 1;

    load_kv(0, 0); CP_COMMIT();
    int buf = 0;
    for (int kt = 0; kt <= ktmax; kt++) {
        const int k0 = kt * 64;
        CP_WAIT0();
        __syncthreads();
        if (kt < ktmax) { load_kv(buf ^ 1, (kt + 1) * 64); CP_COMMIT(); }
        const float* Ks = sm + buf * AT_SZ;
        const float* Vs = sm + (2 + buf) * AT_SZ;

        // S = Q K^T  (b-frag = one float2, K phys-adjacent k-pair)
        float sc[8][4] = {};
        #pragma unroll
        for (int kk = 0; kk < 8; kk++) {
            #pragma unroll
            for (int nt = 0; nt < 8; nt++) {
                float2 kb = *(const float2*)&Ks[(nt * 8 + g) * AT_STR + kk * 8 + 2 * t4];
                mma_tf32(sc[nt], qa[kk][0], qa[kk][1], qa[kk][2], qa[kk][3],
                         __float_as_uint(kb.x), __float_as_uint(kb.y));
            }
        }

        // ALiBi + causal + online softmax (C-frag cols = k0 + nt*8 + 2*t4 + {0,1})
        float mx0 = -1e30f, mx1 = -1e30f;
        #pragma unroll
        for (int nt = 0; nt < 8; nt++) {
            #pragma unroll
            for (int e = 0; e < 4; e++) {
                int col = k0 + nt * 8 + 2 * t4 + (e & 1);
                int row = (e < 2) ? r0 : r1;
                float s = sc[nt][e] + slope * (float)(col - row);
                if (col > row) s = -1e30f;
                sc[nt][e] = s;
            }
            mx0 = fmaxf(mx0, fmaxf(sc[nt][0], sc[nt][1]));
            mx1 = fmaxf(mx1, fmaxf(sc[nt][2], sc[nt][3]));
        }
        mx0 = fmaxf(mx0, __shfl_xor_sync(0xffffffffu, mx0, 1));
        mx0 = fmaxf(mx0, __shfl_xor_sync(0xffffffffu, mx0, 2));
        mx1 = fmaxf(mx1, __shfl_xor_sync(0xffffffffu, mx1, 1));
        mx1 = fmaxf(mx1, __shfl_xor_sync(0xffffffffu, mx1, 2));
        float mn0 = fmaxf(m0r, mx0), mn1 = fmaxf(m1r, mx1);
        float corr0 = __expf(m0r - mn0), corr1 = __expf(m1r - mn1);

        float rs0 = 0.f, rs1 = 0.f;
        #pragma unroll
        for (int nt = 0; nt < 8; nt++) {
            sc[nt][0] = __expf(sc[nt][0] - mn0);
            sc[nt][1] = __expf(sc[nt][1] - mn0);
            sc[nt][2] = __expf(sc[nt][2] - mn1);
            sc[nt][3] = __expf(sc[nt][3] - mn1);
            rs0 += sc[nt][0] + sc[nt][1];
            rs1 += sc[nt][2] + sc[nt][3];
        }
        rs0 += __shfl_xor_sync(0xffffffffu, rs0, 1);
        rs0 += __shfl_xor_sync(0xffffffffu, rs0, 2);
        rs1 += __shfl_xor_sync(0xffffffffu, rs1, 1);
        rs1 += __shfl_xor_sync(0xffffffffu, rs1, 2);
        m0r = mn0; m1r = mn1;
        l0r = l0r * corr0 + rs0;
        l1r = l1r * corr1 + rs1;

        #pragma unroll
        for (int nt = 0; nt < 8; nt++) {
            oc[nt][0] *= corr0; oc[nt][1] *= corr0;
            oc[nt][2] *= corr1; oc[nt][3] *= corr1;
        }

        // O += P @ V : C-frag of S *is* the A-frag under the k-slot permutation:
        // chunk kk = own C-frag tile nt=kk; a = {p0, p2, p1, p3}. No smem for P.
        #pragma unroll
        for (int kk = 0; kk < 8; kk++) {
            uint32_t a0 = f2tf32(sc[kk][0]);
            uint32_t a1 = f2tf32(sc[kk][2]);
            uint32_t a2 = f2tf32(sc[kk][1]);
            uint32_t a3 = f2tf32(sc[kk][3]);
            #pragma unroll
            for (int nt = 0; nt < 8; nt++) {
                float2 vb = *(const float2*)&Vs[(nt * 8 + g) * AT_STR + kk * 8 + 2 * t4];
                mma_tf32(oc[nt], a0, a1, a2, a3,
                         __float_as_uint(vb.x), __float_as_uint(vb.y));
            }
        }
        buf ^= 1;
    }

    // Epilogue: normalize and write y[b, t, h, d]
    float inv0 = 1.f / l0r, inv1 = 1.f / l1r;
    #pragma unroll
    for (int nt = 0; nt < 8; nt++) {
        int d = nt * 8 + 2 * t4;
        *(float2*)&g_y[(((size_t)(b * TT + r0) * HH) + h) * DD + d] =
            make_float2(oc[nt][0] * inv0, oc[nt][1] * inv0);
        *(float2*)&g_y[(((size_t)(b * TT + r1) * HH) + h) * DD + d] =
            make_float2(oc[nt][2] * inv1, oc[nt][3] * inv1);
    }
}

// ---------------------------------------------------------------------------
// Kernel 4: out[b,t,i*64+d] = sum_j y[b,t,j,d] * proj_tmp[i][j]
// ---------------------------------------------------------------------------
__global__ __launch_bounds__(256) void proj_kernel(
    const float* __restrict__ proj_tmp, float* __restrict__ out)
{
    __shared__ float ys[CC];
    __shared__ float wt[HH * HH];
    const int bt  = blockIdx.x;
    const int tid = threadIdx.x;
    wt[tid] = proj_tmp[tid];
    #pragma unroll
    for (int i = tid; i < CC; i += 256) ys[i] = g_y[(size_t)bt * CC + i];
    __syncthreads();
    for (int o = tid; o < CC; o += 256) {
        int i = o >> 6, d = o & 63;
        float s = 0.f;
        #pragma unroll
        for (int j = 0; j < HH; j++) s += ys[j * DD + d] * wt[i * HH + j];
        out[(size_t)bt * CC + o] = s;
    }
}

// ---------------------------------------------------------------------------
extern "C" void kernel_launch(void* const* d_in, const int* in_sizes, int n_in,
                              void* d_out, int out_size)
{
    const float* x     = (const float*)d_in[0];
    const float* W     = (const float*)d_in[1];
    const float* v_tmp = (const float*)d_in[2];
    const float* p_tmp = (const float*)d_in[3];
    float* out = (float*)d_out;
    (void)in_sizes; (void)n_in; (void)out_size;

    preround<<<2048, 256>>>(x, W);

    size_t gsm = (size_t)(2 * GA_SZ + 2 * GB_SZ) * sizeof(float);   // ~70.7 KB
    cudaFuncSetAttribute(gemm_qk_mma,
                         cudaFuncAttributeMaxDynamicSharedMemorySize, (int)gsm);
    gemm_qk_mma<<<dim3(2 * CC / 128, BT / 128), 256, gsm>>>();

    vmix_kernel<<<BT, 256>>>(x, v_tmp);
    vtrans_kernel<<<dim3(TT / 64, BH), 256>>>();

    size_t asm_ = (size_t)(4 * AT_SZ) * sizeof(float);              // ~69.6 KB
    cudaFuncSetAttribute(attn_mma,
                         cudaFuncAttributeMaxDynamicSharedMemorySize, (int)asm_);
    attn_mma<<<dim3(TT / 128, BH), 256, asm_>>>();

    proj_kernel<<<BT, 256>>>(p_tmp, out);
}